// round 6
// baseline (speedup 1.0000x reference)
#include <cuda_runtime.h>

// LSTM: B=32768, T=28, IN=28, H=8, gates i,j,f,o; FORGET_BIAS=1.0
// R6: revert R5 lane-split (SHFL on critical path, dup loads -> regression).
// Instead: 2 batch elements per thread. Each weight LDS.128 feeds 4 fma2
// (LDS:FMA 1:4), 32 independent acc chains -> one warp saturates the FMA
// pipe (fma2 rt_SMSP=2). 512 warps, grid 256: loaded SMs run 1 warp/SMSP.
// Keep R4's window control: rolled x-loop + 1-deep prefetch, h unroll 2.

#define T_STEPS 28
#define IN_DIM 28
#define NH 8
#define NC 10
#define TPB 64

typedef unsigned long long u64;

__device__ __forceinline__ u64 pack2(float lo, float hi) {
    u64 r;
    asm("mov.b64 %0, {%1, %2};" : "=l"(r) : "f"(lo), "f"(hi));
    return r;
}
__device__ __forceinline__ void unpack2(u64 v, float& lo, float& hi) {
    asm("mov.b64 {%0, %1}, %2;" : "=f"(lo), "=f"(hi) : "l"(v));
}
__device__ __forceinline__ u64 fma2(u64 a, u64 b, u64 c) {
    u64 d;
    asm("fma.rn.f32x2 %0, %1, %2, %3;" : "=l"(d) : "l"(a), "l"(b), "l"(c));
    return d;
}
__device__ __forceinline__ float rcp_fast(float x) {
    float r;
    asm("rcp.approx.ftz.f32 %0, %1;" : "=f"(r) : "f"(x));
    return r;
}
__device__ __forceinline__ float ex2_fast(float x) {
    float r;
    asm("ex2.approx.ftz.f32 %0, %1;" : "=f"(r) : "f"(x));
    return r;
}

#define LOG2E 1.4426950408889634f

__device__ __forceinline__ float sigmoid_f(float x) {
    return rcp_fast(1.0f + ex2_fast(-x * LOG2E));
}
__device__ __forceinline__ float tanh_f(float x) {
    return 1.0f - 2.0f * rcp_fast(1.0f + ex2_fast(2.0f * LOG2E * x));
}

// One weight row feeds BOTH elements: 8 LDS.128 -> 32 fma2.
__device__ __forceinline__ void gate_fma2(u64* acc0, u64* acc1,
                                          const u64* sWrow,
                                          float v0, float v1) {
    u64 x0 = pack2(v0, v0);
    u64 x1 = pack2(v1, v1);
    const ulonglong2* wr = reinterpret_cast<const ulonglong2*>(sWrow);
#pragma unroll
    for (int p = 0; p < 8; p++) {
        ulonglong2 w = wr[p];
        acc0[2 * p]     = fma2(x0, w.x, acc0[2 * p]);
        acc0[2 * p + 1] = fma2(x0, w.y, acc0[2 * p + 1]);
        acc1[2 * p]     = fma2(x1, w.x, acc1[2 * p]);
        acc1[2 * p + 1] = fma2(x1, w.y, acc1[2 * p + 1]);
    }
}

__global__ void __launch_bounds__(TPB, 4)   // 255-reg ceiling only
lstm_kernel(const float* __restrict__ x,
            const float* __restrict__ W,     // [36, 32]
            const float* __restrict__ b,     // [32]
            const float* __restrict__ ow,    // [8, 10]
            const float* __restrict__ ob,    // [10]
            float* __restrict__ out,         // [B, 10]
            int B)
{
    // sW[k*16 + g] = (W[k][g], W[k][g+16]), g in [0,16)
    __shared__ __align__(16) u64 sW[36 * 16];
    __shared__ __align__(16) u64 sB[16];
    __shared__ float sOw[NH * NC];
    __shared__ float sOb[NC];

    const int tid = threadIdx.x;

    for (int idx = tid; idx < 36 * 16; idx += TPB) {
        int k = idx >> 4, g = idx & 15;
        sW[idx] = pack2(W[k * 32 + g], W[k * 32 + g + 16]);
    }
    if (tid < 16) {
        float hi = b[tid + 16] + (tid < 8 ? 1.0f : 0.0f);  // FORGET_BIAS in f
        sB[tid] = pack2(b[tid], hi);
    }
    for (int idx = tid; idx < NH * NC; idx += TPB) sOw[idx] = ow[idx];
    if (tid < NC) sOb[tid] = ob[tid];
    __syncthreads();

    const int e0 = (blockIdx.x * TPB + tid) * 2;   // this thread's 2 elements
    if (e0 >= B) return;

    const float4* __restrict__ xin0 =
        reinterpret_cast<const float4*>(x + (size_t)e0 * (T_STEPS * IN_DIM));
    const float4* __restrict__ xin1 =
        reinterpret_cast<const float4*>(x + (size_t)(e0 + 1) * (T_STEPS * IN_DIM));

    float c0[NH], h0[NH], c1[NH], h1[NH];
#pragma unroll
    for (int g = 0; g < NH; g++) {
        c0[g] = 0.0f; h0[g] = 0.0f;
        c1[g] = 0.0f; h1[g] = 0.0f;
    }

#pragma unroll 1
    for (int t = 0; t < T_STEPS; t++) {
        u64 acc0[16], acc1[16];
#pragma unroll
        for (int p = 0; p < 8; p++) {
            ulonglong2 bb = reinterpret_cast<const ulonglong2*>(sB)[p];
            acc0[2 * p] = bb.x;     acc0[2 * p + 1] = bb.y;
            acc1[2 * p] = bb.x;     acc1[2 * p + 1] = bb.y;
        }

        // x contribution: 7 groups of 4 rows, rolled + 1-deep prefetch
        float4 cur0 = xin0[t * 7];
        float4 cur1 = xin1[t * 7];
#pragma unroll 1
        for (int i = 0; i < 7; i++) {
            float4 nxt0 = (i < 6) ? xin0[t * 7 + i + 1] : cur0;
            float4 nxt1 = (i < 6) ? xin1[t * 7 + i + 1] : cur1;
            gate_fma2(acc0, acc1, &sW[(4 * i + 0) * 16], cur0.x, cur1.x);
            gate_fma2(acc0, acc1, &sW[(4 * i + 1) * 16], cur0.y, cur1.y);
            gate_fma2(acc0, acc1, &sW[(4 * i + 2) * 16], cur0.z, cur1.z);
            gate_fma2(acc0, acc1, &sW[(4 * i + 3) * 16], cur0.w, cur1.w);
            cur0 = nxt0;
            cur1 = nxt1;
        }
        // h contribution: 8 rows
#pragma unroll 2
        for (int k = 0; k < NH; k++)
            gate_fma2(acc0, acc1, &sW[(IN_DIM + k) * 16], h0[k], h1[k]);

        // activations: acc[g]=(i_g,f_g), acc[8+g]=(j_g,o_g)
#pragma unroll
        for (int g = 0; g < NH; g++) {
            float ai, af, aj, ao;
            unpack2(acc0[g], ai, af);
            unpack2(acc0[8 + g], aj, ao);
            float cn = c0[g] * sigmoid_f(af) + sigmoid_f(ai) * tanh_f(aj);
            c0[g] = cn;
            h0[g] = tanh_f(cn) * sigmoid_f(ao);

            unpack2(acc1[g], ai, af);
            unpack2(acc1[8 + g], aj, ao);
            cn = c1[g] * sigmoid_f(af) + sigmoid_f(ai) * tanh_f(aj);
            c1[g] = cn;
            h1[g] = tanh_f(cn) * sigmoid_f(ao);
        }
    }

    // output projection for both elements
    float* __restrict__ po0 = out + (size_t)e0 * NC;
    float* __restrict__ po1 = out + (size_t)(e0 + 1) * NC;
#pragma unroll
    for (int cls = 0; cls < NC; cls++) {
        float a0 = sOb[cls], a1 = a0;
#pragma unroll
        for (int k = 0; k < NH; k++) {
            float w = sOw[k * NC + cls];
            a0 += h0[k] * w;
            a1 += h1[k] * w;
        }
        po0[cls] = a0;
        po1[cls] = a1;
    }
}

extern "C" void kernel_launch(void* const* d_in, const int* in_sizes, int n_in,
                              void* d_out, int out_size) {
    const float* x  = (const float*)d_in[0];
    const float* W  = (const float*)d_in[1];
    const float* b  = (const float*)d_in[2];
    const float* ow = (const float*)d_in[3];
    const float* ob = (const float*)d_in[4];
    float* out = (float*)d_out;

    const int B = in_sizes[0] / (T_STEPS * IN_DIM);
    const int threads_total = B / 2;
    const int grid = (threads_total + TPB - 1) / TPB;
    lstm_kernel<<<grid, TPB>>>(x, W, b, ow, ob, out, B);
}